// round 5
// baseline (speedup 1.0000x reference)
#include <cuda_runtime.h>
#include <cstdint>

#define T_STEPS 256
#define BATCH   8
#define NPROBES 4
#define FULLM   0xffffffffu

typedef unsigned long long ull;

// ---------- f32x2 packed helpers (sm_103a) ----------
__device__ __forceinline__ ull pack2(float lo, float hi) {
    ull r; asm("mov.b64 %0, {%1, %2};" : "=l"(r) : "f"(lo), "f"(hi)); return r;
}
__device__ __forceinline__ void unpack2(ull a, float& lo, float& hi) {
    asm("mov.b64 {%0, %1}, %2;" : "=f"(lo), "=f"(hi) : "l"(a));
}
__device__ __forceinline__ float lo2(ull a) { float x, y; unpack2(a, x, y); return x; }
__device__ __forceinline__ float hi2(ull a) { float x, y; unpack2(a, x, y); return y; }
__device__ __forceinline__ ull add2(ull a, ull b) {
    ull r; asm("add.rn.f32x2 %0, %1, %2;" : "=l"(r) : "l"(a), "l"(b)); return r;
}
__device__ __forceinline__ ull fma2(ull a, ull b, ull c) {
    ull r; asm("fma.rn.f32x2 %0, %1, %2, %3;" : "=l"(r) : "l"(a), "l"(b), "l"(c)); return r;
}

__device__ float    g_psum[NPROBES] = {0.f, 0.f, 0.f, 0.f};
__device__ unsigned g_ticket        = 0u;

// dynamic smem (bytes):
//   [0, 65536)     kk_sh : ull[512][16]  per-thread packed kk (generic path only)
//   [65536, 98304) halo  : float[2][32][128]
//   [98304, 99328) xsh   : float[256]
#define SMEM_BYTES 99328

// State layout per thread (vertical-pair packing, stride 4):
//   y1[c][k] = ( y(r0+k, c0+c), y(r0+k+4, c0+c) ),  c,k in 0..3
// above(p_k) = p_{k-1} (k>0), below(p_k) = p_{k+1} (k<3): existing registers.
// left(col c) = y2[c-1] (old values after commit), right = y1[c+1] (still old).
template <bool UNI>
__device__ __forceinline__ void sim_loop(
    float* __restrict__ halo, const float* __restrict__ xsh,
    const ull* __restrict__ kk_sh, ull Kc,
    ull (&y1)[4][4], ull (&y2)[4][4],
    int w, int l, int c0, bool src_owner,
    bool pown, const int (&pidx)[NPROBES], float (&pacc)[NPROBES],
    ull NEG4, ull CY2P, ull TWO2P)
{
    const bool l0 = (l == 0), l31 = (l == 31);
    int cur = 0;
    for (int t = 0; t < T_STEPS; t++) {
        // previous step's neighbor boundary rows
        float4 u = make_float4(0.f, 0.f, 0.f, 0.f), d = u;
        const float* hb = halo + cur * 4096;
        if (w > 0)  u = *reinterpret_cast<const float4*>(&hb[(2 * (w - 1) + 1) * 128 + c0]);
        if (w < 15) d = *reinterpret_cast<const float4*>(&hb[(2 * (w + 1) + 0) * 128 + c0]);

        // edge-column shuffles of whole packs (old values)
        ull L[4], R[4];
#pragma unroll
        for (int k = 0; k < 4; k++) {
            L[k] = __shfl_up_sync(FULLM,  y1[3][k], 1);
            R[k] = __shfl_down_sync(FULLM, y1[0][k], 1);
            if (l0)  L[k] = 0ull;
            if (l31) R[k] = 0ull;
        }

#pragma unroll
        for (int c = 0; c < 4; c++) {
            const float uc = (c == 0) ? u.x : (c == 1) ? u.y : (c == 2) ? u.z : u.w;
            const float dc = (c == 0) ? d.x : (c == 1) ? d.y : (c == 2) ? d.z : d.w;
            const ull A0 = pack2(uc, lo2(y1[c][3]));   // (row r0-1, row r0+3)
            const ull B3 = pack2(hi2(y1[c][0]), dc);   // (row r0+4, row r0+8)

            ull nv[4];
#pragma unroll
            for (int k = 0; k < 4; k++) {
                const ull lf = (c == 0) ? L[k] : y2[c - 1][k];   // old col c-1
                const ull rt = (c == 3) ? R[k] : y1[c + 1][k];   // old col c+1
                const ull A  = (k == 0) ? A0 : y1[c][k - 1];
                const ull B  = (k == 3) ? B3 : y1[c][k + 1];
                ull s   = add2(add2(A, B), add2(lf, rt));
                ull lap = fma2(NEG4, y1[c][k], s);
                ull kk  = UNI ? Kc : kk_sh[c * 4 + k];
                nv[k]   = fma2(kk, lap, fma2(CY2P, y2[c][k], TWO2P));
            }
#pragma unroll
            for (int k = 0; k < 4; k++) { y2[c][k] = y1[c][k]; y1[c][k] = nv[k]; }
        }

        // source injection at (64,64): w==8 (k=0, lo half), lane 16, col 0
        if (src_owner) {
            float a, b2; unpack2(y1[0][0], a, b2);
            a += xsh[t];
            y1[0][0] = pack2(a, b2);
        }

        // probe accumulation (<=4 owning threads)
        if (pown) {
#pragma unroll
            for (int p = 0; p < NPROBES; p++) {
                if (pidx[p] >= 0) {
                    float val = 0.f;
                    switch (pidx[p]) {
#define GC2(JL, CL) case (JL)*4+(CL): \
                        val = ((JL) < 4) ? lo2(y1[CL][(JL) & 3]) : hi2(y1[CL][(JL) & 3]); break;
#define GCROW(JL) GC2(JL, 0) GC2(JL, 1) GC2(JL, 2) GC2(JL, 3)
                        GCROW(0) GCROW(1) GCROW(2) GCROW(3)
                        GCROW(4) GCROW(5) GCROW(6) GCROW(7)
#undef GCROW
#undef GC2
                    }
                    pacc[p] += val * val;
                }
            }
        }

        // publish boundary rows r0 (lo of k=0) and r0+7 (hi of k=3)
        float* hb2 = halo + (cur ^ 1) * 4096;
        float4 top, bot;
        top.x = lo2(y1[0][0]); top.y = lo2(y1[1][0]); top.z = lo2(y1[2][0]); top.w = lo2(y1[3][0]);
        bot.x = hi2(y1[0][3]); bot.y = hi2(y1[1][3]); bot.z = hi2(y1[2][3]); bot.w = hi2(y1[3][3]);
        *reinterpret_cast<float4*>(&hb2[(2 * w + 0) * 128 + c0]) = top;
        *reinterpret_cast<float4*>(&hb2[(2 * w + 1) * 128 + c0]) = bot;

        __syncthreads();
        cur ^= 1;
    }
}

__global__ __launch_bounds__(512, 1)
void wave_fused_kernel(const float* __restrict__ x,
                       const float* __restrict__ c,
                       const int* __restrict__ probes_i32,
                       float* __restrict__ out)
{
    extern __shared__ char smem_raw[];
    ull*   kk_all = reinterpret_cast<ull*>(smem_raw);
    float* halo   = reinterpret_cast<float*>(smem_raw + 65536);
    float* xsh    = reinterpret_cast<float*>(smem_raw + 98304);

    const int b   = blockIdx.x;
    const int tid = threadIdx.x;
    const int w   = tid >> 5;
    const int l   = tid & 31;
    const int r0  = w << 3;
    const int c0  = l << 2;

    const float dtb   = 0.5f * 0.005f;
    const float cy2s  = -1.0f - dtb;                   // -1.0025
    const float denom = 4.0f + (0.5f * 0.005f) / 0.5f; // 4.005
    const float invd  = 1.0f / denom;

    const ull NEG4  = pack2(-4.0f, -4.0f);
    const ull CY2P  = pack2(cy2s * invd, cy2s * invd);
    const ull TWO2P = pack2(2.0f * invd, 2.0f * invd);

    for (int t = tid; t < T_STEPS; t += 512)
        xsh[t] = x[t * BATCH + b];
    for (int i = tid; i < 2 * 32 * 128; i += 512)
        halo[65536 / 4 - 65536 / 4 + i] = 0.f;   // halo[i]
    // (note: halo already points at the right base; plain zero loop)
    // fill per-thread kk (generic path) + uniformity check + zero state
    ull* kk_sh = kk_all + tid * 16;
    const float cref = c[0];
    bool all_eq = true;
    ull y1[4][4], y2[4][4];
#pragma unroll
    for (int cc = 0; cc < 4; cc++) {
#pragma unroll
        for (int k = 0; k < 4; k++) {
            float ca = c[(r0 + k)     * 128 + c0 + cc];
            float cb = c[(r0 + k + 4) * 128 + c0 + cc];
            all_eq = all_eq && (ca == cref) && (cb == cref);
            kk_sh[cc * 4 + k] = pack2(0.25f * ca * ca * invd,
                                      0.25f * cb * cb * invd);
            y1[cc][k] = 0ull; y2[cc][k] = 0ull;
        }
    }
    const float kc = 0.25f * cref * cref * invd;
    const ull   Kc = pack2(kc, kc);

    // probe decoding (runtime dtype detection: int32 vs int64)
    int pxv[NPROBES], pyv[NPROBES];
    {
        int odd_or = probes_i32[1] | probes_i32[3] | probes_i32[5] | probes_i32[7];
        if (odd_or == 0) {
#pragma unroll
            for (int p = 0; p < NPROBES; p++) {
                pxv[p] = probes_i32[4 * p];
                pyv[p] = probes_i32[4 * p + 2];
            }
        } else {
#pragma unroll
            for (int p = 0; p < NPROBES; p++) {
                pxv[p] = probes_i32[2 * p];
                pyv[p] = probes_i32[2 * p + 1];
            }
        }
    }

    float pacc[NPROBES];
    int   pidx[NPROBES];
    bool  pown = false;
#pragma unroll
    for (int p = 0; p < NPROBES; p++) {
        pacc[p] = 0.f;
        int px = pxv[p], py = pyv[p];
        bool mine = (px >= r0) && (px < r0 + 8) && (py >= c0) && (py < c0 + 4);
        pidx[p] = mine ? ((px - r0) * 4 + (py - c0)) : -1;
        pown = pown || mine;
    }

    const bool src_owner = (w == 8) && (l == 16);

    const int uni = __syncthreads_and(all_eq ? 1 : 0);  // also the init barrier

    if (uni)
        sim_loop<true >(halo, xsh, kk_sh, Kc, y1, y2, w, l, c0, src_owner,
                        pown, pidx, pacc, NEG4, CY2P, TWO2P);
    else
        sim_loop<false>(halo, xsh, kk_sh, Kc, y1, y2, w, l, c0, src_owner,
                        pown, pidx, pacc, NEG4, CY2P, TWO2P);

#pragma unroll
    for (int p = 0; p < NPROBES; p++)
        if (pidx[p] >= 0) atomicAdd(&g_psum[p], pacc[p]);

    // fused finalization: last CTA reduces, writes out, resets globals
    __syncthreads();
    __threadfence();
    if (tid == 0) {
        unsigned ticket = atomicAdd(&g_ticket, 1u);
        if (ticket == BATCH - 1) {
            float v[NPROBES];
            float s = 0.f;
#pragma unroll
            for (int p = 0; p < NPROBES; p++) {
                v[p] = atomicAdd(&g_psum[p], 0.0f);
                s += v[p];
            }
#pragma unroll
            for (int p = 0; p < NPROBES; p++) {
                out[p] = v[p] / s;
                atomicExch(&g_psum[p], 0.0f);
            }
            atomicExch(&g_ticket, 0u);
        }
    }
}

extern "C" void kernel_launch(void* const* d_in, const int* in_sizes, int n_in,
                              void* d_out, int out_size)
{
    const float* x      = (const float*)d_in[0];   // (256, 8) f32
    const float* c      = (const float*)d_in[1];   // (128, 128) f32
    const int*   probes = (const int*)d_in[2];     // (4, 2) i32/i64 — detected in-kernel
    float*       out    = (float*)d_out;           // (4,) f32

    cudaFuncSetAttribute(wave_fused_kernel,
                         cudaFuncAttributeMaxDynamicSharedMemorySize, SMEM_BYTES);

    wave_fused_kernel<<<BATCH, 512, SMEM_BYTES>>>(x, c, probes, out);
}

// round 6
// speedup vs baseline: 1.7283x; 1.7283x over previous
#include <cuda_runtime.h>
#include <cstdint>

#define T_STEPS 256
#define BATCH   8
#define NPROBES 4
#define NTHREADS 1024
#define FULLM   0xffffffffu

typedef unsigned long long ull;

// ---------- f32x2 packed helpers (sm_103a) ----------
__device__ __forceinline__ ull pack2(float lo, float hi) {
    ull r; asm("mov.b64 %0, {%1, %2};" : "=l"(r) : "f"(lo), "f"(hi)); return r;
}
__device__ __forceinline__ void unpack2(ull a, float& lo, float& hi) {
    asm("mov.b64 {%0, %1}, %2;" : "=f"(lo), "=f"(hi) : "l"(a));
}
__device__ __forceinline__ ull add2(ull a, ull b) {
    ull r; asm("add.rn.f32x2 %0, %1, %2;" : "=l"(r) : "l"(a), "l"(b)); return r;
}
__device__ __forceinline__ ull fma2(ull a, ull b, ull c) {
    ull r; asm("fma.rn.f32x2 %0, %1, %2, %3;" : "=l"(r) : "l"(a), "l"(b), "l"(c)); return r;
}

// zero-initialized at load; last CTA resets after reading -> every replay clean
__device__ float    g_psum[NPROBES] = {0.f, 0.f, 0.f, 0.f};
__device__ unsigned g_ticket        = 0u;

// dynamic smem (bytes):
//   [0, 65536)        kk2  : ull[128][64]   0.25*c^2*invd packed pairs
//   [65536, 131072)   halo : ull[2][64][64] boundary rows (64 slots = 2 per warp)
//   [131072, 132096)  xsh  : float[256]
#define SMEM_BYTES 132096

__global__ __launch_bounds__(NTHREADS, 1)
void wave_fused_kernel(const float* __restrict__ x,
                       const float* __restrict__ c,
                       const int* __restrict__ probes_i32,
                       float* __restrict__ out)
{
    extern __shared__ char smem_raw[];
    ull*   kk2  = reinterpret_cast<ull*>(smem_raw);            // [row*64 + pair]
    ull*   halo = reinterpret_cast<ull*>(smem_raw + 65536);    // [buf*4096 + slot*64 + pair]
    float* xsh  = reinterpret_cast<float*>(smem_raw + 131072);

    const int b   = blockIdx.x;
    const int tid = threadIdx.x;
    const int w   = tid >> 5;      // warp 0..31 : rows 4w..4w+3
    const int l   = tid & 31;      // lane       : cols 4l..4l+3
    const int r0  = w << 2;
    const int c0  = l << 2;

    // constants (reference-exact, folded by invd)
    const float dtb   = 0.5f * 0.005f;
    const float cy2s  = -1.0f - dtb;                   // -1.0025
    const float denom = 4.0f + (0.5f * 0.005f) / 0.5f; // 4.005
    const float invd  = 1.0f / denom;

    const ull NEG4  = pack2(-4.0f, -4.0f);
    const ull CY2P  = pack2(cy2s * invd, cy2s * invd);
    const ull TWO2P = pack2(2.0f * invd, 2.0f * invd);

    // preload source signal for this batch
    for (int t = tid; t < T_STEPS; t += NTHREADS)
        xsh[t] = x[t * BATCH + b];

    // zero halo buffers
    for (int i = tid; i < 2 * 64 * 64; i += NTHREADS)
        halo[i] = 0ull;

    // fill kk' = 0.25*c^2*invd into shared; init register state (4 rows x 4 cols)
    ull y1lo[4], y1hi[4], y2lo[4], y2hi[4];
#pragma unroll
    for (int j = 0; j < 4; j++) {
        float4 cv = *reinterpret_cast<const float4*>(&c[(r0 + j) * 128 + c0]);
        kk2[(r0 + j) * 64 + 2 * l]     = pack2(0.25f * cv.x * cv.x * invd,
                                               0.25f * cv.y * cv.y * invd);
        kk2[(r0 + j) * 64 + 2 * l + 1] = pack2(0.25f * cv.z * cv.z * invd,
                                               0.25f * cv.w * cv.w * invd);
        y1lo[j] = 0ull; y1hi[j] = 0ull;
        y2lo[j] = 0ull; y2hi[j] = 0ull;
    }

    // ---- probe decoding (runtime dtype detection: int32 vs int64) ----
    int pxv[NPROBES], pyv[NPROBES];
    {
        int odd_or = probes_i32[1] | probes_i32[3] | probes_i32[5] | probes_i32[7];
        if (odd_or == 0) {
#pragma unroll
            for (int p = 0; p < NPROBES; p++) {
                pxv[p] = probes_i32[4 * p];
                pyv[p] = probes_i32[4 * p + 2];
            }
        } else {
#pragma unroll
            for (int p = 0; p < NPROBES; p++) {
                pxv[p] = probes_i32[2 * p];
                pyv[p] = probes_i32[2 * p + 1];
            }
        }
    }

    float pacc[NPROBES];
    int   pidx[NPROBES];          // 4*j + comp, or -1
    bool  pown = false;
#pragma unroll
    for (int p = 0; p < NPROBES; p++) {
        pacc[p] = 0.f;
        int px = pxv[p], py = pyv[p];
        bool mine = (px >= r0) && (px < r0 + 4) && (py >= c0) && (py < c0 + 4);
        pidx[p] = mine ? ((px - r0) * 4 + (py - c0)) : -1;
        pown = pown || mine;
    }

    // source (64,64): row 64 -> warp 16, j=0; col 64 -> lane 16, comp 0 (lo of lo)
    const bool src_owner = (w == 16) && (l == 16);

    __syncthreads();

    int cur = 0;
    for (int t = 0; t < T_STEPS; t++) {
        // old boundary rows of neighbor warps
        ull up_lo = 0, up_hi = 0, dn_lo = 0, dn_hi = 0;
        if (w > 0) {
            ulonglong2 h = *reinterpret_cast<const ulonglong2*>(
                &halo[cur * 4096 + (2 * (w - 1) + 1) * 64 + 2 * l]);
            up_lo = h.x; up_hi = h.y;
        }
        if (w < 31) {
            ulonglong2 h = *reinterpret_cast<const ulonglong2*>(
                &halo[cur * 4096 + (2 * (w + 1) + 0) * 64 + 2 * l]);
            dn_lo = h.x; dn_hi = h.y;
        }
        const float xt  = src_owner ? xsh[t] : 0.0f;
        const ull   xt2 = pack2(xt, 0.0f);

        ull above_lo = up_lo, above_hi = up_hi;
#pragma unroll
        for (int j = 0; j < 4; j++) {
            const ull v_lo = y1lo[j], v_hi = y1hi[j];
            ull below_lo = dn_lo, below_hi = dn_hi;
            if (j < 3) { below_lo = y1lo[j + 1]; below_hi = y1hi[j + 1]; }

            float vx, vy, vz, vw;
            unpack2(v_lo, vx, vy);
            unpack2(v_hi, vz, vw);

            float lf = __shfl_up_sync(FULLM, vw, 1);
            float rt = __shfl_down_sync(FULLM, vx, 1);
            if (l == 0)  lf = 0.f;
            if (l == 31) rt = 0.f;

            const ull P1 = pack2(lf, vx);
            const ull P2 = pack2(vy, vz);
            const ull P3 = pack2(vw, rt);

            ull lap_lo = add2(add2(above_lo, below_lo), add2(P1, P2));
            lap_lo = fma2(NEG4, v_lo, lap_lo);
            ull lap_hi = add2(add2(above_hi, below_hi), add2(P2, P3));
            lap_hi = fma2(NEG4, v_hi, lap_hi);

            const ulonglong2 kkp = *reinterpret_cast<const ulonglong2*>(
                &kk2[(r0 + j) * 64 + 2 * l]);

            ull nv_lo = fma2(kkp.x, lap_lo, fma2(CY2P, y2lo[j], TWO2P));
            ull nv_hi = fma2(kkp.y, lap_hi, fma2(CY2P, y2hi[j], TWO2P));

            if (j == 0) nv_lo = add2(nv_lo, xt2);   // source injection (0 elsewhere)

            y2lo[j] = v_lo;  y2hi[j] = v_hi;
            y1lo[j] = nv_lo; y1hi[j] = nv_hi;
            above_lo = v_lo; above_hi = v_hi;
        }

        // probe accumulation (only the <=4 owning threads take the branch)
        if (pown) {
#pragma unroll
            for (int p = 0; p < NPROBES; p++) {
                if (pidx[p] >= 0) {
                    float a, bf, val = 0.f;
                    switch (pidx[p]) {
#define GC(J) \
                        case 4*(J)+0: unpack2(y1lo[J], a, bf); val = a;  break; \
                        case 4*(J)+1: unpack2(y1lo[J], a, bf); val = bf; break; \
                        case 4*(J)+2: unpack2(y1hi[J], a, bf); val = a;  break; \
                        case 4*(J)+3: unpack2(y1hi[J], a, bf); val = bf; break;
                        GC(0) GC(1) GC(2) GC(3)
#undef GC
                    }
                    pacc[p] += val * val;
                }
            }
        }

        // publish new boundary rows (4w and 4w+3)
        {
            ulonglong2 top; top.x = y1lo[0]; top.y = y1hi[0];
            ulonglong2 bot; bot.x = y1lo[3]; bot.y = y1hi[3];
            *reinterpret_cast<ulonglong2*>(&halo[(cur ^ 1) * 4096 + (2 * w + 0) * 64 + 2 * l]) = top;
            *reinterpret_cast<ulonglong2*>(&halo[(cur ^ 1) * 4096 + (2 * w + 1) * 64 + 2 * l]) = bot;
        }
        __syncthreads();
        cur ^= 1;
    }

#pragma unroll
    for (int p = 0; p < NPROBES; p++)
        if (pidx[p] >= 0) atomicAdd(&g_psum[p], pacc[p]);

    // fused finalization: last CTA reduces, writes out, resets globals
    __syncthreads();
    __threadfence();
    if (tid == 0) {
        unsigned ticket = atomicAdd(&g_ticket, 1u);
        if (ticket == BATCH - 1) {
            float v[NPROBES];
            float s = 0.f;
#pragma unroll
            for (int p = 0; p < NPROBES; p++) {
                v[p] = atomicAdd(&g_psum[p], 0.0f);
                s += v[p];
            }
#pragma unroll
            for (int p = 0; p < NPROBES; p++) {
                out[p] = v[p] / s;
                atomicExch(&g_psum[p], 0.0f);
            }
            atomicExch(&g_ticket, 0u);
        }
    }
}

extern "C" void kernel_launch(void* const* d_in, const int* in_sizes, int n_in,
                              void* d_out, int out_size)
{
    const float* x      = (const float*)d_in[0];   // (256, 8) f32
    const float* c      = (const float*)d_in[1];   // (128, 128) f32
    const int*   probes = (const int*)d_in[2];     // (4, 2) i32/i64 — detected in-kernel
    float*       out    = (float*)d_out;           // (4,) f32

    cudaFuncSetAttribute(wave_fused_kernel,
                         cudaFuncAttributeMaxDynamicSharedMemorySize, SMEM_BYTES);

    wave_fused_kernel<<<BATCH, NTHREADS, SMEM_BYTES>>>(x, c, probes, out);
}

// round 7
// speedup vs baseline: 2.0370x; 1.1786x over previous
#include <cuda_runtime.h>
#include <cstdint>

#define T_STEPS 256
#define BATCH   8
#define NPROBES 4
#define NTHREADS 1024
#define NCTAS   (BATCH * 2)
#define FULLM   0xffffffffu

typedef unsigned long long ull;

// ---------- f32x2 packed helpers (sm_103a) ----------
__device__ __forceinline__ ull pack2(float lo, float hi) {
    ull r; asm("mov.b64 %0, {%1, %2};" : "=l"(r) : "f"(lo), "f"(hi)); return r;
}
__device__ __forceinline__ void unpack2(ull a, float& lo, float& hi) {
    asm("mov.b64 {%0, %1}, %2;" : "=f"(lo), "=f"(hi) : "l"(a));
}
__device__ __forceinline__ ull add2(ull a, ull b) {
    ull r; asm("add.rn.f32x2 %0, %1, %2;" : "=l"(r) : "l"(a), "l"(b)); return r;
}
__device__ __forceinline__ ull fma2(ull a, ull b, ull c) {
    ull r; asm("fma.rn.f32x2 %0, %1, %2, %3;" : "=l"(r) : "l"(a), "l"(b), "l"(c)); return r;
}

// ---------- cluster / mbarrier helpers ----------
__device__ __forceinline__ uint32_t smem_u32(const void* p) {
    uint32_t a;
    asm("{ .reg .u64 t; cvta.to.shared.u64 t, %1; cvt.u32.u64 %0, t; }" : "=r"(a) : "l"(p));
    return a;
}
__device__ __forceinline__ uint32_t mapa_u32(uint32_t addr, uint32_t rank) {
    uint32_t r; asm("mapa.shared::cluster.u32 %0, %1, %2;" : "=r"(r) : "r"(addr), "r"(rank));
    return r;
}
__device__ __forceinline__ void st_cluster_v2(uint32_t addr, ull a, ull b) {
    asm volatile("st.shared::cluster.v2.u64 [%0], {%1, %2};" :: "r"(addr), "l"(a), "l"(b) : "memory");
}
__device__ __forceinline__ void mbar_init(uint32_t addr, uint32_t cnt) {
    asm volatile("mbarrier.init.shared.b64 [%0], %1;" :: "r"(addr), "r"(cnt) : "memory");
}
__device__ __forceinline__ void mbar_arrive_remote(uint32_t addr) {
    asm volatile("mbarrier.arrive.release.cluster.shared::cluster.b64 _, [%0];" :: "r"(addr) : "memory");
}
__device__ __forceinline__ void mbar_wait_cluster(uint32_t addr, uint32_t ph) {
    uint32_t done;
    asm volatile("{\n\t.reg .pred p;\n\t"
                 "mbarrier.try_wait.parity.acquire.cluster.shared::cta.b64 p, [%1], %2;\n\t"
                 "selp.b32 %0, 1, 0, p;\n\t}"
                 : "=r"(done) : "r"(addr), "r"(ph) : "memory");
    while (!done) {
        asm volatile("{\n\t.reg .pred p;\n\t"
                     "mbarrier.try_wait.parity.acquire.cluster.shared::cta.b64 p, [%1], %2;\n\t"
                     "selp.b32 %0, 1, 0, p;\n\t}"
                     : "=r"(done) : "r"(addr), "r"(ph) : "memory");
    }
}
__device__ __forceinline__ void cluster_sync() {
    asm volatile("barrier.cluster.arrive.aligned;" ::: "memory");
    asm volatile("barrier.cluster.wait.aligned;"   ::: "memory");
}

__device__ float    g_psum[NPROBES] = {0.f, 0.f, 0.f, 0.f};
__device__ unsigned g_ticket        = 0u;

// dynamic smem (bytes):
//   [0, 65536)      halo : ull[2][64][64]   all 64 local rows, double-buffered
//   [65536, 66560)  rbuf : ull[2][64]       peer-pushed boundary row, double-buffered
//   [66560, 67584)  xsh  : float[256]
//   [67584, 67600)  rmbar: ull[2]
#define SMEM_BYTES 67616

__global__ __launch_bounds__(NTHREADS, 1) __cluster_dims__(2, 1, 1)
void wave_fused_kernel(const float* __restrict__ x,
                       const float* __restrict__ c,
                       const int* __restrict__ probes_i32,
                       float* __restrict__ out)
{
    extern __shared__ char smem_raw[];
    ull*   halo = reinterpret_cast<ull*>(smem_raw);
    ull*   rbuf = reinterpret_cast<ull*>(smem_raw + 65536);
    float* xsh  = reinterpret_cast<float*>(smem_raw + 66560);

    const uint32_t smem_base = smem_u32(smem_raw);
    const uint32_t mbar_base = smem_base + 67584;

    uint32_t rank; asm("mov.u32 %0, %%cluster_ctarank;" : "=r"(rank));
    const int b   = blockIdx.x >> 1;          // batch = cluster id
    const int tid = threadIdx.x;
    const int w   = tid >> 5;                 // warp 0..31 : local rows 2w, 2w+1
    const int l   = tid & 31;                 // lane       : cols 4l..4l+3
    const int c0  = l << 2;
    const int gr0 = (int)rank * 64 + 2 * w;   // global row of j=0

    // constants (reference-exact, folded by invd)
    const float dtb   = 0.5f * 0.005f;
    const float cy2s  = -1.0f - dtb;                   // -1.0025
    const float denom = 4.0f + (0.5f * 0.005f) / 0.5f; // 4.005
    const float invd  = 1.0f / denom;

    const ull NEG4  = pack2(-4.0f, -4.0f);
    const ull CY2P  = pack2(cy2s * invd, cy2s * invd);
    const ull TWO2P = pack2(2.0f * invd, 2.0f * invd);

    for (int t = tid; t < T_STEPS; t += NTHREADS)
        xsh[t] = x[t * BATCH + b];
    for (int i = tid; i < 2 * 64 * 64; i += NTHREADS)
        halo[i] = 0ull;

    // kk' = 0.25*c^2*invd in REGISTERS (2 rows x 2 packed pairs)
    ull kkx[2], kky[2], y1lo[2], y1hi[2], y2lo[2], y2hi[2];
#pragma unroll
    for (int j = 0; j < 2; j++) {
        float4 cv = *reinterpret_cast<const float4*>(&c[(gr0 + j) * 128 + c0]);
        kkx[j] = pack2(0.25f * cv.x * cv.x * invd, 0.25f * cv.y * cv.y * invd);
        kky[j] = pack2(0.25f * cv.z * cv.z * invd, 0.25f * cv.w * cv.w * invd);
        y1lo[j] = 0ull; y1hi[j] = 0ull; y2lo[j] = 0ull; y2hi[j] = 0ull;
    }

    // ---- probe decoding (runtime dtype detection: int32 vs int64) ----
    int pxv[NPROBES], pyv[NPROBES];
    {
        int odd_or = probes_i32[1] | probes_i32[3] | probes_i32[5] | probes_i32[7];
        if (odd_or == 0) {
#pragma unroll
            for (int p = 0; p < NPROBES; p++) { pxv[p] = probes_i32[4 * p]; pyv[p] = probes_i32[4 * p + 2]; }
        } else {
#pragma unroll
            for (int p = 0; p < NPROBES; p++) { pxv[p] = probes_i32[2 * p]; pyv[p] = probes_i32[2 * p + 1]; }
        }
    }
    float pacc[NPROBES];
    int   pidx[NPROBES];          // j*4 + comp (j in 0..1), or -1
    bool  pown = false;
#pragma unroll
    for (int p = 0; p < NPROBES; p++) {
        pacc[p] = 0.f;
        int px = pxv[p], py = pyv[p];
        bool mine = (px >= gr0) && (px < gr0 + 2) && (py >= c0) && (py < c0 + 4);
        pidx[p] = mine ? ((px - gr0) * 4 + (py - c0)) : -1;
        pown = pown || mine;
    }

    // source (64,64): rank 1, local row 0 -> warp 0 j=0; lane 16 comp 0
    const bool src_owner = (rank == 1) && (w == 0) && (l == 16);

    // cross-CTA roles: rank0's warp31 (bottom edge) <-> rank1's warp0 (top edge)
    const bool edge_warp = (rank == 0) ? (w == 31) : (w == 0);
    const uint32_t peer = rank ^ 1u;
    const uint32_t peer_rbuf = mapa_u32(smem_base + 65536, peer);
    const uint32_t peer_mbar = mapa_u32(mbar_base, peer);

    if (tid == 0) { mbar_init(mbar_base, 32); mbar_init(mbar_base + 8, 32); }
    cluster_sync();   // mbar init + smem zero visible cluster-wide

    int cur = 0;
    for (int t = 0; t < T_STEPS; t++) {
        // neighbors: above of j=0, below of j=1
        ull ab_lo = 0, ab_hi = 0, bl_lo = 0, bl_hi = 0;
        if (edge_warp && t > 0) {
            const int rb = (t - 1) & 1;
            mbar_wait_cluster(mbar_base + rb * 8, ((t - 1) >> 1) & 1);
            ulonglong2 h = *reinterpret_cast<const ulonglong2*>(&rbuf[rb * 64 + 2 * l]);
            if (rank == 0) { bl_lo = h.x; bl_hi = h.y; }   // below comes from peer
            else           { ab_lo = h.x; ab_hi = h.y; }   // above comes from peer
        }
        if (w > 0) {
            ulonglong2 h = *reinterpret_cast<const ulonglong2*>(
                &halo[cur * 4096 + (2 * w - 1) * 64 + 2 * l]);
            ab_lo = h.x; ab_hi = h.y;
        }
        if (w < 31) {
            ulonglong2 h = *reinterpret_cast<const ulonglong2*>(
                &halo[cur * 4096 + (2 * w + 2) * 64 + 2 * l]);
            bl_lo = h.x; bl_hi = h.y;
        }

        const float xt  = src_owner ? xsh[t] : 0.0f;
        const ull   xt2 = pack2(xt, 0.0f);

        ull above_lo = ab_lo, above_hi = ab_hi;
#pragma unroll
        for (int j = 0; j < 2; j++) {
            const ull v_lo = y1lo[j], v_hi = y1hi[j];
            ull below_lo = bl_lo, below_hi = bl_hi;
            if (j < 1) { below_lo = y1lo[1]; below_hi = y1hi[1]; }

            float vx, vy, vz, vw;
            unpack2(v_lo, vx, vy);
            unpack2(v_hi, vz, vw);

            float lf = __shfl_up_sync(FULLM, vw, 1);
            float rt = __shfl_down_sync(FULLM, vx, 1);
            if (l == 0)  lf = 0.f;
            if (l == 31) rt = 0.f;

            const ull P1 = pack2(lf, vx);
            const ull P2 = pack2(vy, vz);
            const ull P3 = pack2(vw, rt);

            ull lap_lo = add2(add2(above_lo, below_lo), add2(P1, P2));
            lap_lo = fma2(NEG4, v_lo, lap_lo);
            ull lap_hi = add2(add2(above_hi, below_hi), add2(P2, P3));
            lap_hi = fma2(NEG4, v_hi, lap_hi);

            ull nv_lo = fma2(kkx[j], lap_lo, fma2(CY2P, y2lo[j], TWO2P));
            ull nv_hi = fma2(kky[j], lap_hi, fma2(CY2P, y2hi[j], TWO2P));

            if (j == 0) nv_lo = add2(nv_lo, xt2);   // source (0 for non-owners)

            y2lo[j] = v_lo;  y2hi[j] = v_hi;
            y1lo[j] = nv_lo; y1hi[j] = nv_hi;
            above_lo = v_lo; above_hi = v_hi;
        }

        // probe accumulation (<=4 owning threads)
        if (pown) {
#pragma unroll
            for (int p = 0; p < NPROBES; p++) {
                if (pidx[p] >= 0) {
                    float a, bf, val = 0.f;
                    switch (pidx[p]) {
                        case 0: unpack2(y1lo[0], a, bf); val = a;  break;
                        case 1: unpack2(y1lo[0], a, bf); val = bf; break;
                        case 2: unpack2(y1hi[0], a, bf); val = a;  break;
                        case 3: unpack2(y1hi[0], a, bf); val = bf; break;
                        case 4: unpack2(y1lo[1], a, bf); val = a;  break;
                        case 5: unpack2(y1lo[1], a, bf); val = bf; break;
                        case 6: unpack2(y1hi[1], a, bf); val = a;  break;
                        case 7: unpack2(y1hi[1], a, bf); val = bf; break;
                    }
                    pacc[p] += val * val;
                }
            }
        }

        // publish both rows into local halo (other buffer)
        {
            ulonglong2 r0v; r0v.x = y1lo[0]; r0v.y = y1hi[0];
            ulonglong2 r1v; r1v.x = y1lo[1]; r1v.y = y1hi[1];
            *reinterpret_cast<ulonglong2*>(&halo[(cur ^ 1) * 4096 + (2 * w + 0) * 64 + 2 * l]) = r0v;
            *reinterpret_cast<ulonglong2*>(&halo[(cur ^ 1) * 4096 + (2 * w + 1) * 64 + 2 * l]) = r1v;
        }

        // push boundary row to peer CTA (skip last step: nobody reads it)
        if (edge_warp && t < T_STEPS - 1) {
            const int wb = t & 1;
            ull s_lo, s_hi;
            if (rank == 0) { s_lo = y1lo[1]; s_hi = y1hi[1]; }   // my bottom row (global 63)
            else           { s_lo = y1lo[0]; s_hi = y1hi[0]; }   // my top row    (global 64)
            st_cluster_v2(peer_rbuf + (wb * 64 + 2 * l) * 8, s_lo, s_hi);
            mbar_arrive_remote(peer_mbar + wb * 8);              // all 32 lanes arrive (release)
        }

        __syncthreads();
        cur ^= 1;
    }

#pragma unroll
    for (int p = 0; p < NPROBES; p++)
        if (pidx[p] >= 0) atomicAdd(&g_psum[p], pacc[p]);

    // fused finalization: last of 16 CTAs reduces, writes out, resets globals
    __syncthreads();
    __threadfence();
    if (tid == 0) {
        unsigned ticket = atomicAdd(&g_ticket, 1u);
        if (ticket == NCTAS - 1) {
            float v[NPROBES];
            float s = 0.f;
#pragma unroll
            for (int p = 0; p < NPROBES; p++) { v[p] = atomicAdd(&g_psum[p], 0.0f); s += v[p]; }
#pragma unroll
            for (int p = 0; p < NPROBES; p++) {
                out[p] = v[p] / s;
                atomicExch(&g_psum[p], 0.0f);
            }
            atomicExch(&g_ticket, 0u);
        }
    }
}

extern "C" void kernel_launch(void* const* d_in, const int* in_sizes, int n_in,
                              void* d_out, int out_size)
{
    const float* x      = (const float*)d_in[0];   // (256, 8) f32
    const float* c      = (const float*)d_in[1];   // (128, 128) f32
    const int*   probes = (const int*)d_in[2];     // (4, 2) i32/i64 — detected in-kernel
    float*       out    = (float*)d_out;           // (4,) f32

    cudaFuncSetAttribute(wave_fused_kernel,
                         cudaFuncAttributeMaxDynamicSharedMemorySize, SMEM_BYTES);

    wave_fused_kernel<<<NCTAS, NTHREADS, SMEM_BYTES>>>(x, c, probes, out);
}

// round 8
// speedup vs baseline: 2.1238x; 1.0426x over previous
#include <cuda_runtime.h>
#include <cstdint>

#define T_STEPS 256
#define BATCH   8
#define NPROBES 4
#define NTHREADS 1024
#define NCTAS   (BATCH * 2)
#define FULLM   0xffffffffu

typedef unsigned long long ull;

// ---------- f32x2 packed helpers (sm_103a) ----------
__device__ __forceinline__ ull pack2(float lo, float hi) {
    ull r; asm("mov.b64 %0, {%1, %2};" : "=l"(r) : "f"(lo), "f"(hi)); return r;
}
__device__ __forceinline__ void unpack2(ull a, float& lo, float& hi) {
    asm("mov.b64 {%0, %1}, %2;" : "=f"(lo), "=f"(hi) : "l"(a));
}
__device__ __forceinline__ ull add2(ull a, ull b) {
    ull r; asm("add.rn.f32x2 %0, %1, %2;" : "=l"(r) : "l"(a), "l"(b)); return r;
}
__device__ __forceinline__ ull fma2(ull a, ull b, ull c) {
    ull r; asm("fma.rn.f32x2 %0, %1, %2, %3;" : "=l"(r) : "l"(a), "l"(b), "l"(c)); return r;
}

// ---------- cluster / mbarrier / acq-rel helpers ----------
__device__ __forceinline__ uint32_t smem_u32(const void* p) {
    uint32_t a;
    asm("{ .reg .u64 t; cvta.to.shared.u64 t, %1; cvt.u32.u64 %0, t; }" : "=r"(a) : "l"(p));
    return a;
}
__device__ __forceinline__ uint32_t mapa_u32(uint32_t addr, uint32_t rank) {
    uint32_t r; asm("mapa.shared::cluster.u32 %0, %1, %2;" : "=r"(r) : "r"(addr), "r"(rank));
    return r;
}
__device__ __forceinline__ void st_cluster_v2(uint32_t addr, ull a, ull b) {
    asm volatile("st.shared::cluster.v2.u64 [%0], {%1, %2};" :: "r"(addr), "l"(a), "l"(b) : "memory");
}
__device__ __forceinline__ void mbar_init(uint32_t addr, uint32_t cnt) {
    asm volatile("mbarrier.init.shared.b64 [%0], %1;" :: "r"(addr), "r"(cnt) : "memory");
}
__device__ __forceinline__ void mbar_arrive_remote(uint32_t addr) {
    asm volatile("mbarrier.arrive.release.cluster.shared::cluster.b64 _, [%0];" :: "r"(addr) : "memory");
}
__device__ __forceinline__ void mbar_wait_cluster(uint32_t addr, uint32_t ph) {
    uint32_t done;
    asm volatile("{\n\t.reg .pred p;\n\t"
                 "mbarrier.try_wait.parity.acquire.cluster.shared::cta.b64 p, [%1], %2;\n\t"
                 "selp.b32 %0, 1, 0, p;\n\t}"
                 : "=r"(done) : "r"(addr), "r"(ph) : "memory");
    while (!done) {
        asm volatile("{\n\t.reg .pred p;\n\t"
                     "mbarrier.try_wait.parity.acquire.cluster.shared::cta.b64 p, [%1], %2;\n\t"
                     "selp.b32 %0, 1, 0, p;\n\t}"
                     : "=r"(done) : "r"(addr), "r"(ph) : "memory");
    }
}
__device__ __forceinline__ void cluster_sync() {
    asm volatile("barrier.cluster.arrive.aligned;" ::: "memory");
    asm volatile("barrier.cluster.wait.aligned;"   ::: "memory");
}
__device__ __forceinline__ int ld_acq(uint32_t a) {
    int v; asm volatile("ld.acquire.cta.shared.s32 %0, [%1];" : "=r"(v) : "r"(a) : "memory");
    return v;
}
__device__ __forceinline__ void st_rel(uint32_t a, int v) {
    asm volatile("st.release.cta.shared.s32 [%0], %1;" :: "r"(a), "r"(v) : "memory");
}

__device__ float    g_psum[NPROBES] = {0.f, 0.f, 0.f, 0.f};
__device__ unsigned g_ticket        = 0u;

// dynamic smem (bytes):
//   [0, 65536)       halo  : ull[2][64][64]   local rows, double-buffered (step t -> buf[t&1])
//   [65536, 66560)   rbuf  : ull[2][64]       peer-pushed boundary row
//   [66560, 67584)   xsh   : float[256]
//   [67584, 67600)   rmbar : ull[2]
//   [67600, 71696)   flags : int[32][32]      per-warp per-lane step counters
#define SMEM_BYTES 71712

__global__ __launch_bounds__(NTHREADS, 1) __cluster_dims__(2, 1, 1)
void wave_fused_kernel(const float* __restrict__ x,
                       const float* __restrict__ c,
                       const int* __restrict__ probes_i32,
                       float* __restrict__ out)
{
    extern __shared__ char smem_raw[];
    ull*   halo  = reinterpret_cast<ull*>(smem_raw);
    ull*   rbuf  = reinterpret_cast<ull*>(smem_raw + 65536);
    float* xsh   = reinterpret_cast<float*>(smem_raw + 66560);
    int*   flags = reinterpret_cast<int*>(smem_raw + 67600);

    const uint32_t smem_base  = smem_u32(smem_raw);
    const uint32_t mbar_base  = smem_base + 67584;
    const uint32_t flags_base = smem_base + 67600;

    uint32_t rank; asm("mov.u32 %0, %%cluster_ctarank;" : "=r"(rank));
    const int b   = blockIdx.x >> 1;          // batch = cluster id
    const int tid = threadIdx.x;
    const int w   = tid >> 5;                 // warp 0..31 : local rows 2w, 2w+1
    const int l   = tid & 31;                 // lane       : cols 4l..4l+3
    const int c0  = l << 2;
    const int gr0 = (int)rank * 64 + 2 * w;   // global row of j=0

    // constants (reference-exact, folded by invd)
    const float dtb   = 0.5f * 0.005f;
    const float cy2s  = -1.0f - dtb;                   // -1.0025
    const float denom = 4.0f + (0.5f * 0.005f) / 0.5f; // 4.005
    const float invd  = 1.0f / denom;

    const ull NEG4  = pack2(-4.0f, -4.0f);
    const ull CY2P  = pack2(cy2s * invd, cy2s * invd);
    const ull TWO2P = pack2(2.0f * invd, 2.0f * invd);

    for (int t = tid; t < T_STEPS; t += NTHREADS)
        xsh[t] = x[t * BATCH + b];
    for (int i = tid; i < 2 * 64 * 64; i += NTHREADS)
        halo[i] = 0ull;
    flags[tid & 1023] = -1;                   // flags[w][l] = -1 (1024 entries)

    // kk' = 0.25*c^2*invd in REGISTERS (2 rows x 2 packed pairs)
    ull kkx[2], kky[2], y1lo[2], y1hi[2], y2lo[2], y2hi[2];
#pragma unroll
    for (int j = 0; j < 2; j++) {
        float4 cv = *reinterpret_cast<const float4*>(&c[(gr0 + j) * 128 + c0]);
        kkx[j] = pack2(0.25f * cv.x * cv.x * invd, 0.25f * cv.y * cv.y * invd);
        kky[j] = pack2(0.25f * cv.z * cv.z * invd, 0.25f * cv.w * cv.w * invd);
        y1lo[j] = 0ull; y1hi[j] = 0ull; y2lo[j] = 0ull; y2hi[j] = 0ull;
    }

    // ---- probe decoding (runtime dtype detection: int32 vs int64) ----
    int pxv[NPROBES], pyv[NPROBES];
    {
        int odd_or = probes_i32[1] | probes_i32[3] | probes_i32[5] | probes_i32[7];
        if (odd_or == 0) {
#pragma unroll
            for (int p = 0; p < NPROBES; p++) { pxv[p] = probes_i32[4 * p]; pyv[p] = probes_i32[4 * p + 2]; }
        } else {
#pragma unroll
            for (int p = 0; p < NPROBES; p++) { pxv[p] = probes_i32[2 * p]; pyv[p] = probes_i32[2 * p + 1]; }
        }
    }
    float pacc[NPROBES];
    int   pidx[NPROBES];          // j*4 + comp (j in 0..1), or -1
    bool  pown = false;
#pragma unroll
    for (int p = 0; p < NPROBES; p++) {
        pacc[p] = 0.f;
        int px = pxv[p], py = pyv[p];
        bool mine = (px >= gr0) && (px < gr0 + 2) && (py >= c0) && (py < c0 + 4);
        pidx[p] = mine ? ((px - gr0) * 4 + (py - c0)) : -1;
        pown = pown || mine;
    }

    // source (64,64): rank 1, local row 0 -> warp 0 j=0; lane 16 comp 0
    const bool src_owner = (rank == 1) && (w == 0) && (l == 16);

    // cross-CTA roles: rank0's warp31 (bottom edge) <-> rank1's warp0 (top edge)
    const bool edge_warp = (rank == 0) ? (w == 31) : (w == 0);
    const uint32_t peer = rank ^ 1u;
    const uint32_t peer_rbuf = mapa_u32(smem_base + 65536, peer);
    const uint32_t peer_mbar = mapa_u32(mbar_base, peer);

    // per-lane flag addresses
    const uint32_t myflag = flags_base + ((w << 5) + l) * 4;
    const uint32_t upflag = myflag - 128;   // flags[w-1][l]
    const uint32_t dnflag = myflag + 128;   // flags[w+1][l]

    if (tid == 0) { mbar_init(mbar_base, 32); mbar_init(mbar_base + 8, 32); }
    __syncthreads();   // local init done
    cluster_sync();    // mbar init + smem zero visible cluster-wide

    for (int t = 0; t < T_STEPS; t++) {
        const int need = t - 1;
        const int rdbuf = (t + 1) & 1;   // neighbor data of step t-1 (zeros for t=0)
        const int wrbuf = t & 1;

        // neighbors: above of j=0, below of j=1
        ull ab_lo = 0, ab_hi = 0, bl_lo = 0, bl_hi = 0;
        if (edge_warp && t > 0) {
            const int rb = (t - 1) & 1;
            mbar_wait_cluster(mbar_base + rb * 8, ((t - 1) >> 1) & 1);
            ulonglong2 h = *reinterpret_cast<const ulonglong2*>(&rbuf[rb * 64 + 2 * l]);
            if (rank == 0) { bl_lo = h.x; bl_hi = h.y; }   // below from peer
            else           { ab_lo = h.x; ab_hi = h.y; }   // above from peer
        }
        if (w > 0) {
            while (ld_acq(upflag) < need) { }
            ulonglong2 h = *reinterpret_cast<const ulonglong2*>(
                &halo[rdbuf * 4096 + (2 * w - 1) * 64 + 2 * l]);
            ab_lo = h.x; ab_hi = h.y;
        }
        if (w < 31) {
            while (ld_acq(dnflag) < need) { }
            ulonglong2 h = *reinterpret_cast<const ulonglong2*>(
                &halo[rdbuf * 4096 + (2 * w + 2) * 64 + 2 * l]);
            bl_lo = h.x; bl_hi = h.y;
        }

        const float xt  = src_owner ? xsh[t] : 0.0f;
        const ull   xt2 = pack2(xt, 0.0f);

        ull above_lo = ab_lo, above_hi = ab_hi;
#pragma unroll
        for (int j = 0; j < 2; j++) {
            const ull v_lo = y1lo[j], v_hi = y1hi[j];
            ull below_lo = bl_lo, below_hi = bl_hi;
            if (j < 1) { below_lo = y1lo[1]; below_hi = y1hi[1]; }

            float vx, vy, vz, vw;
            unpack2(v_lo, vx, vy);
            unpack2(v_hi, vz, vw);

            float lf = __shfl_up_sync(FULLM, vw, 1);
            float rt = __shfl_down_sync(FULLM, vx, 1);
            if (l == 0)  lf = 0.f;
            if (l == 31) rt = 0.f;

            const ull P1 = pack2(lf, vx);
            const ull P2 = pack2(vy, vz);
            const ull P3 = pack2(vw, rt);

            ull lap_lo = add2(add2(above_lo, below_lo), add2(P1, P2));
            lap_lo = fma2(NEG4, v_lo, lap_lo);
            ull lap_hi = add2(add2(above_hi, below_hi), add2(P2, P3));
            lap_hi = fma2(NEG4, v_hi, lap_hi);

            ull nv_lo = fma2(kkx[j], lap_lo, fma2(CY2P, y2lo[j], TWO2P));
            ull nv_hi = fma2(kky[j], lap_hi, fma2(CY2P, y2hi[j], TWO2P));

            if (j == 0) nv_lo = add2(nv_lo, xt2);   // source (0 for non-owners)

            y2lo[j] = v_lo;  y2hi[j] = v_hi;
            y1lo[j] = nv_lo; y1hi[j] = nv_hi;
            above_lo = v_lo; above_hi = v_hi;
        }

        // probe accumulation (<=4 owning threads)
        if (pown) {
#pragma unroll
            for (int p = 0; p < NPROBES; p++) {
                if (pidx[p] >= 0) {
                    float a, bf, val = 0.f;
                    switch (pidx[p]) {
                        case 0: unpack2(y1lo[0], a, bf); val = a;  break;
                        case 1: unpack2(y1lo[0], a, bf); val = bf; break;
                        case 2: unpack2(y1hi[0], a, bf); val = a;  break;
                        case 3: unpack2(y1hi[0], a, bf); val = bf; break;
                        case 4: unpack2(y1lo[1], a, bf); val = a;  break;
                        case 5: unpack2(y1lo[1], a, bf); val = bf; break;
                        case 6: unpack2(y1hi[1], a, bf); val = a;  break;
                        case 7: unpack2(y1hi[1], a, bf); val = bf; break;
                    }
                    pacc[p] += val * val;
                }
            }
        }

        // publish both rows into halo buf[t&1]; release per-lane flag
        {
            ulonglong2 r0v; r0v.x = y1lo[0]; r0v.y = y1hi[0];
            ulonglong2 r1v; r1v.x = y1lo[1]; r1v.y = y1hi[1];
            *reinterpret_cast<ulonglong2*>(&halo[wrbuf * 4096 + (2 * w + 0) * 64 + 2 * l]) = r0v;
            *reinterpret_cast<ulonglong2*>(&halo[wrbuf * 4096 + (2 * w + 1) * 64 + 2 * l]) = r1v;
        }
        st_rel(myflag, t);

        // push boundary row to peer CTA (skip last step: nobody reads it)
        if (edge_warp && t < T_STEPS - 1) {
            const int wb = t & 1;
            ull s_lo, s_hi;
            if (rank == 0) { s_lo = y1lo[1]; s_hi = y1hi[1]; }   // bottom row (global 63)
            else           { s_lo = y1lo[0]; s_hi = y1hi[0]; }   // top row    (global 64)
            st_cluster_v2(peer_rbuf + (wb * 64 + 2 * l) * 8, s_lo, s_hi);
            mbar_arrive_remote(peer_mbar + wb * 8);              // 32 lanes arrive (release)
        }
    }

#pragma unroll
    for (int p = 0; p < NPROBES; p++)
        if (pidx[p] >= 0) atomicAdd(&g_psum[p], pacc[p]);

    // fused finalization: last of 16 CTAs reduces, writes out, resets globals
    __syncthreads();
    __threadfence();
    if (tid == 0) {
        unsigned ticket = atomicAdd(&g_ticket, 1u);
        if (ticket == NCTAS - 1) {
            float v[NPROBES];
            float s = 0.f;
#pragma unroll
            for (int p = 0; p < NPROBES; p++) { v[p] = atomicAdd(&g_psum[p], 0.0f); s += v[p]; }
#pragma unroll
            for (int p = 0; p < NPROBES; p++) {
                out[p] = v[p] / s;
                atomicExch(&g_psum[p], 0.0f);
            }
            atomicExch(&g_ticket, 0u);
        }
    }
}

extern "C" void kernel_launch(void* const* d_in, const int* in_sizes, int n_in,
                              void* d_out, int out_size)
{
    const float* x      = (const float*)d_in[0];   // (256, 8) f32
    const float* c      = (const float*)d_in[1];   // (128, 128) f32
    const int*   probes = (const int*)d_in[2];     // (4, 2) i32/i64 — detected in-kernel
    float*       out    = (float*)d_out;           // (4,) f32

    cudaFuncSetAttribute(wave_fused_kernel,
                         cudaFuncAttributeMaxDynamicSharedMemorySize, SMEM_BYTES);

    wave_fused_kernel<<<NCTAS, NTHREADS, SMEM_BYTES>>>(x, c, probes, out);
}

// round 9
// speedup vs baseline: 2.5863x; 1.2177x over previous
#include <cuda_runtime.h>
#include <cstdint>

#define T_STEPS 256
#define BATCH   8
#define NPROBES 4
#define NTHREADS 1024
#define NCTAS   (BATCH * 2)
#define FULLM   0xffffffffu

typedef unsigned long long ull;

// ---------- f32x2 packed helpers (sm_103a) ----------
__device__ __forceinline__ ull pack2(float lo, float hi) {
    ull r; asm("mov.b64 %0, {%1, %2};" : "=l"(r) : "f"(lo), "f"(hi)); return r;
}
__device__ __forceinline__ void unpack2(ull a, float& lo, float& hi) {
    asm("mov.b64 {%0, %1}, %2;" : "=f"(lo), "=f"(hi) : "l"(a));
}
__device__ __forceinline__ ull add2(ull a, ull b) {
    ull r; asm("add.rn.f32x2 %0, %1, %2;" : "=l"(r) : "l"(a), "l"(b)); return r;
}
__device__ __forceinline__ ull fma2(ull a, ull b, ull c) {
    ull r; asm("fma.rn.f32x2 %0, %1, %2, %3;" : "=l"(r) : "l"(a), "l"(b), "l"(c)); return r;
}

// ---------- cluster / mbarrier helpers ----------
__device__ __forceinline__ uint32_t smem_u32(const void* p) {
    uint32_t a;
    asm("{ .reg .u64 t; cvta.to.shared.u64 t, %1; cvt.u32.u64 %0, t; }" : "=r"(a) : "l"(p));
    return a;
}
__device__ __forceinline__ uint32_t mapa_u32(uint32_t addr, uint32_t rank) {
    uint32_t r; asm("mapa.shared::cluster.u32 %0, %1, %2;" : "=r"(r) : "r"(addr), "r"(rank));
    return r;
}
__device__ __forceinline__ void st_cluster_v2(uint32_t addr, ull a, ull b) {
    asm volatile("st.shared::cluster.v2.u64 [%0], {%1, %2};" :: "r"(addr), "l"(a), "l"(b) : "memory");
}
__device__ __forceinline__ void mbar_init(uint32_t addr, uint32_t cnt) {
    asm volatile("mbarrier.init.shared.b64 [%0], %1;" :: "r"(addr), "r"(cnt) : "memory");
}
__device__ __forceinline__ void mbar_arrive_local(uint32_t addr) {
    asm volatile("mbarrier.arrive.release.cta.shared::cta.b64 _, [%0];" :: "r"(addr) : "memory");
}
__device__ __forceinline__ void mbar_arrive_remote(uint32_t addr) {
    asm volatile("mbarrier.arrive.release.cluster.shared::cluster.b64 _, [%0];" :: "r"(addr) : "memory");
}
// HW-sleep waits (suspend-time hint enables TRYWAIT sleep path)
__device__ __forceinline__ void mbar_wait_cta(uint32_t addr, uint32_t ph) {
    uint32_t done;
    do {
        asm volatile("{\n\t.reg .pred p;\n\t"
                     "mbarrier.try_wait.parity.acquire.cta.shared::cta.b64 p, [%1], %2, 0x989680;\n\t"
                     "selp.b32 %0, 1, 0, p;\n\t}"
                     : "=r"(done) : "r"(addr), "r"(ph) : "memory");
    } while (!done);
}
__device__ __forceinline__ void mbar_wait_cluster(uint32_t addr, uint32_t ph) {
    uint32_t done;
    do {
        asm volatile("{\n\t.reg .pred p;\n\t"
                     "mbarrier.try_wait.parity.acquire.cluster.shared::cta.b64 p, [%1], %2, 0x989680;\n\t"
                     "selp.b32 %0, 1, 0, p;\n\t}"
                     : "=r"(done) : "r"(addr), "r"(ph) : "memory");
    } while (!done);
}
__device__ __forceinline__ void cluster_sync() {
    asm volatile("barrier.cluster.arrive.aligned;" ::: "memory");
    asm volatile("barrier.cluster.wait.aligned;"   ::: "memory");
}

__device__ float    g_psum[NPROBES] = {0.f, 0.f, 0.f, 0.f};
__device__ unsigned g_ticket        = 0u;

// dynamic smem (bytes):
//   [0, 65536)      halo : ull[2][64][64]  local rows, buf = t&1
//   [65536, 66560)  rbuf : ull[2][64]      peer-pushed boundary row
//   [66560, 67584)  xsh  : float[256]
//   [67584, 68096)  wmbar: ull[32][2]      per-warp arrival barriers
#define SMEM_BYTES 68112

__global__ __launch_bounds__(NTHREADS, 1) __cluster_dims__(2, 1, 1)
void wave_fused_kernel(const float* __restrict__ x,
                       const float* __restrict__ c,
                       const int* __restrict__ probes_i32,
                       float* __restrict__ out)
{
    extern __shared__ char smem_raw[];
    ull*   halo = reinterpret_cast<ull*>(smem_raw);
    ull*   rbuf = reinterpret_cast<ull*>(smem_raw + 65536);
    float* xsh  = reinterpret_cast<float*>(smem_raw + 66560);

    const uint32_t smem_base  = smem_u32(smem_raw);
    const uint32_t wmbar_base = smem_base + 67584;   // wmbar[w][bi] at +(w*2+bi)*8

    uint32_t rank; asm("mov.u32 %0, %%cluster_ctarank;" : "=r"(rank));
    const int b   = blockIdx.x >> 1;          // batch = cluster id
    const int tid = threadIdx.x;
    const int w   = tid >> 5;                 // warp 0..31 : local rows 2w, 2w+1
    const int l   = tid & 31;                 // lane       : cols 4l..4l+3
    const int c0  = l << 2;
    const int gr0 = (int)rank * 64 + 2 * w;   // global row of j=0

    // constants (reference-exact, folded by invd)
    const float dtb   = 0.5f * 0.005f;
    const float cy2s  = -1.0f - dtb;                   // -1.0025
    const float denom = 4.0f + (0.5f * 0.005f) / 0.5f; // 4.005
    const float invd  = 1.0f / denom;

    const ull NEG4  = pack2(-4.0f, -4.0f);
    const ull CY2P  = pack2(cy2s * invd, cy2s * invd);
    const ull TWO2P = pack2(2.0f * invd, 2.0f * invd);

    for (int t = tid; t < T_STEPS; t += NTHREADS)
        xsh[t] = x[t * BATCH + b];
    for (int i = tid; i < 2 * 64 * 64; i += NTHREADS)
        halo[i] = 0ull;

    // kk' = 0.25*c^2*invd in REGISTERS (2 rows x 2 packed pairs)
    ull kkx[2], kky[2], y1lo[2], y1hi[2], y2lo[2], y2hi[2];
#pragma unroll
    for (int j = 0; j < 2; j++) {
        float4 cv = *reinterpret_cast<const float4*>(&c[(gr0 + j) * 128 + c0]);
        kkx[j] = pack2(0.25f * cv.x * cv.x * invd, 0.25f * cv.y * cv.y * invd);
        kky[j] = pack2(0.25f * cv.z * cv.z * invd, 0.25f * cv.w * cv.w * invd);
        y1lo[j] = 0ull; y1hi[j] = 0ull; y2lo[j] = 0ull; y2hi[j] = 0ull;
    }

    // ---- probe decoding (runtime dtype detection: int32 vs int64) ----
    int pxv[NPROBES], pyv[NPROBES];
    {
        int odd_or = probes_i32[1] | probes_i32[3] | probes_i32[5] | probes_i32[7];
        if (odd_or == 0) {
#pragma unroll
            for (int p = 0; p < NPROBES; p++) { pxv[p] = probes_i32[4 * p]; pyv[p] = probes_i32[4 * p + 2]; }
        } else {
#pragma unroll
            for (int p = 0; p < NPROBES; p++) { pxv[p] = probes_i32[2 * p]; pyv[p] = probes_i32[2 * p + 1]; }
        }
    }
    float pacc[NPROBES];
    int   pidx[NPROBES];          // j*4 + comp (j in 0..1), or -1
    bool  pown = false;
#pragma unroll
    for (int p = 0; p < NPROBES; p++) {
        pacc[p] = 0.f;
        int px = pxv[p], py = pyv[p];
        bool mine = (px >= gr0) && (px < gr0 + 2) && (py >= c0) && (py < c0 + 4);
        pidx[p] = mine ? ((px - gr0) * 4 + (py - c0)) : -1;
        pown = pown || mine;
    }

    // source (64,64): rank 1, local row 0 -> warp 0 j=0; lane 16 comp 0
    const bool src_owner = (rank == 1) && (w == 0) && (l == 16);

    // cross-CTA roles: rank0's warp31 (bottom edge) <-> rank1's warp0 (top edge)
    const bool edge_warp = (rank == 0) ? (w == 31) : (w == 0);
    const uint32_t peer = rank ^ 1u;
    const uint32_t peer_rbuf = mapa_u32(smem_base + 65536, peer);
    // peer edge warp index: rank0 pushes to rank1's w0, rank1 pushes to rank0's w31
    const int peer_edge_w = (rank == 0) ? 0 : 31;
    const uint32_t peer_wmbar = mapa_u32(wmbar_base + (peer_edge_w * 2) * 8, peer);

    // my mbar addresses
    const uint32_t my_mbar = wmbar_base + (w * 2) * 8;
    const uint32_t up_mbar = wmbar_base + ((w - 1) * 2) * 8;   // neighbor above
    const uint32_t dn_mbar = wmbar_base + ((w + 1) * 2) * 8;   // neighbor below

    // init my two mbars (one thread per warp)
    if (l == 0) {
        // arrivals per use: 32 per local neighbor warp, +32 remote for cluster edge
        uint32_t cnt = 64;
        if ((rank == 0 && w == 0) || (rank == 1 && w == 31)) cnt = 32;
        mbar_init(my_mbar, cnt);
        mbar_init(my_mbar + 8, cnt);
    }
    __syncthreads();   // local init + smem zero done
    cluster_sync();    // visible cluster-wide before any remote arrive

    for (int t = 0; t < T_STEPS; t++) {
        const int rdbuf = (t + 1) & 1;   // buffer holding step t-1 data
        const int wrbuf = t & 1;

        // wait for both neighbors' step-(t-1) data (single HW-sleep wait)
        if (t > 0) {
            const uint32_t mb = my_mbar + ((t - 1) & 1) * 8;
            const uint32_t ph = ((t - 1) >> 1) & 1;
            if (edge_warp) mbar_wait_cluster(mb, ph);
            else           mbar_wait_cta(mb, ph);
        }

        // neighbors: above of j=0, below of j=1
        ull ab_lo = 0, ab_hi = 0, bl_lo = 0, bl_hi = 0;
        if (edge_warp && t > 0) {
            ulonglong2 h = *reinterpret_cast<const ulonglong2*>(&rbuf[((t - 1) & 1) * 64 + 2 * l]);
            if (rank == 0) { bl_lo = h.x; bl_hi = h.y; }   // below from peer
            else           { ab_lo = h.x; ab_hi = h.y; }   // above from peer
        }
        if (w > 0) {
            ulonglong2 h = *reinterpret_cast<const ulonglong2*>(
                &halo[rdbuf * 4096 + (2 * w - 1) * 64 + 2 * l]);
            ab_lo = h.x; ab_hi = h.y;
        }
        if (w < 31) {
            ulonglong2 h = *reinterpret_cast<const ulonglong2*>(
                &halo[rdbuf * 4096 + (2 * w + 2) * 64 + 2 * l]);
            bl_lo = h.x; bl_hi = h.y;
        }

        const float xt  = src_owner ? xsh[t] : 0.0f;
        const ull   xt2 = pack2(xt, 0.0f);

        ull above_lo = ab_lo, above_hi = ab_hi;
#pragma unroll
        for (int j = 0; j < 2; j++) {
            const ull v_lo = y1lo[j], v_hi = y1hi[j];
            ull below_lo = bl_lo, below_hi = bl_hi;
            if (j < 1) { below_lo = y1lo[1]; below_hi = y1hi[1]; }

            float vx, vy, vz, vw;
            unpack2(v_lo, vx, vy);
            unpack2(v_hi, vz, vw);

            float lf = __shfl_up_sync(FULLM, vw, 1);
            float rt = __shfl_down_sync(FULLM, vx, 1);
            if (l == 0)  lf = 0.f;
            if (l == 31) rt = 0.f;

            const ull P1 = pack2(lf, vx);
            const ull P2 = pack2(vy, vz);
            const ull P3 = pack2(vw, rt);

            ull lap_lo = add2(add2(above_lo, below_lo), add2(P1, P2));
            lap_lo = fma2(NEG4, v_lo, lap_lo);
            ull lap_hi = add2(add2(above_hi, below_hi), add2(P2, P3));
            lap_hi = fma2(NEG4, v_hi, lap_hi);

            ull nv_lo = fma2(kkx[j], lap_lo, fma2(CY2P, y2lo[j], TWO2P));
            ull nv_hi = fma2(kky[j], lap_hi, fma2(CY2P, y2hi[j], TWO2P));

            if (j == 0) nv_lo = add2(nv_lo, xt2);   // source (0 for non-owners)

            y2lo[j] = v_lo;  y2hi[j] = v_hi;
            y1lo[j] = nv_lo; y1hi[j] = nv_hi;
            above_lo = v_lo; above_hi = v_hi;
        }

        // probe accumulation (<=4 owning threads)
        if (pown) {
#pragma unroll
            for (int p = 0; p < NPROBES; p++) {
                if (pidx[p] >= 0) {
                    float a, bf, val = 0.f;
                    switch (pidx[p]) {
                        case 0: unpack2(y1lo[0], a, bf); val = a;  break;
                        case 1: unpack2(y1lo[0], a, bf); val = bf; break;
                        case 2: unpack2(y1hi[0], a, bf); val = a;  break;
                        case 3: unpack2(y1hi[0], a, bf); val = bf; break;
                        case 4: unpack2(y1lo[1], a, bf); val = a;  break;
                        case 5: unpack2(y1lo[1], a, bf); val = bf; break;
                        case 6: unpack2(y1hi[1], a, bf); val = a;  break;
                        case 7: unpack2(y1hi[1], a, bf); val = bf; break;
                    }
                    pacc[p] += val * val;
                }
            }
        }

        // publish rows + arrive on neighbors (skip after last step: no consumer)
        if (t < T_STEPS - 1) {
            ulonglong2 r0v; r0v.x = y1lo[0]; r0v.y = y1hi[0];
            ulonglong2 r1v; r1v.x = y1lo[1]; r1v.y = y1hi[1];
            *reinterpret_cast<ulonglong2*>(&halo[wrbuf * 4096 + (2 * w + 0) * 64 + 2 * l]) = r0v;
            *reinterpret_cast<ulonglong2*>(&halo[wrbuf * 4096 + (2 * w + 1) * 64 + 2 * l]) = r1v;

            if (w > 0)  mbar_arrive_local(up_mbar + wrbuf * 8);
            if (w < 31) mbar_arrive_local(dn_mbar + wrbuf * 8);

            if (edge_warp) {
                ull s_lo, s_hi;
                if (rank == 0) { s_lo = y1lo[1]; s_hi = y1hi[1]; }   // bottom row (global 63)
                else           { s_lo = y1lo[0]; s_hi = y1hi[0]; }   // top row    (global 64)
                st_cluster_v2(peer_rbuf + (wrbuf * 64 + 2 * l) * 8, s_lo, s_hi);
                mbar_arrive_remote(peer_wmbar + wrbuf * 8);          // 32 remote arrives
            }
        }
    }

#pragma unroll
    for (int p = 0; p < NPROBES; p++)
        if (pidx[p] >= 0) atomicAdd(&g_psum[p], pacc[p]);

    // fused finalization: last of 16 CTAs reduces, writes out, resets globals
    __syncthreads();
    __threadfence();
    if (tid == 0) {
        unsigned ticket = atomicAdd(&g_ticket, 1u);
        if (ticket == NCTAS - 1) {
            float v[NPROBES];
            float s = 0.f;
#pragma unroll
            for (int p = 0; p < NPROBES; p++) { v[p] = atomicAdd(&g_psum[p], 0.0f); s += v[p]; }
#pragma unroll
            for (int p = 0; p < NPROBES; p++) {
                out[p] = v[p] / s;
                atomicExch(&g_psum[p], 0.0f);
            }
            atomicExch(&g_ticket, 0u);
        }
    }
}

extern "C" void kernel_launch(void* const* d_in, const int* in_sizes, int n_in,
                              void* d_out, int out_size)
{
    const float* x      = (const float*)d_in[0];   // (256, 8) f32
    const float* c      = (const float*)d_in[1];   // (128, 128) f32
    const int*   probes = (const int*)d_in[2];     // (4, 2) i32/i64 — detected in-kernel
    float*       out    = (float*)d_out;           // (4,) f32

    cudaFuncSetAttribute(wave_fused_kernel,
                         cudaFuncAttributeMaxDynamicSharedMemorySize, SMEM_BYTES);

    wave_fused_kernel<<<NCTAS, NTHREADS, SMEM_BYTES>>>(x, c, probes, out);
}

// round 10
// speedup vs baseline: 2.7685x; 1.0705x over previous
#include <cuda_runtime.h>
#include <cstdint>

#define T_STEPS 256
#define BATCH   8
#define NPROBES 4
#define NTHREADS 1024
#define CLUSTER 4
#define NCTAS   (BATCH * CLUSTER)
#define FULLM   0xffffffffu

typedef unsigned long long ull;

// ---------- f32x2 packed helpers (sm_103a) ----------
__device__ __forceinline__ ull pack2(float lo, float hi) {
    ull r; asm("mov.b64 %0, {%1, %2};" : "=l"(r) : "f"(lo), "f"(hi)); return r;
}
__device__ __forceinline__ void unpack2(ull a, float& lo, float& hi) {
    asm("mov.b64 {%0, %1}, %2;" : "=f"(lo), "=f"(hi) : "l"(a));
}
__device__ __forceinline__ ull add2(ull a, ull b) {
    ull r; asm("add.rn.f32x2 %0, %1, %2;" : "=l"(r) : "l"(a), "l"(b)); return r;
}
__device__ __forceinline__ ull fma2(ull a, ull b, ull c) {
    ull r; asm("fma.rn.f32x2 %0, %1, %2, %3;" : "=l"(r) : "l"(a), "l"(b), "l"(c)); return r;
}

// ---------- cluster / mbarrier helpers ----------
__device__ __forceinline__ uint32_t smem_u32(const void* p) {
    uint32_t a;
    asm("{ .reg .u64 t; cvta.to.shared.u64 t, %1; cvt.u32.u64 %0, t; }" : "=r"(a) : "l"(p));
    return a;
}
__device__ __forceinline__ uint32_t mapa_u32(uint32_t addr, uint32_t rank) {
    uint32_t r; asm("mapa.shared::cluster.u32 %0, %1, %2;" : "=r"(r) : "r"(addr), "r"(rank));
    return r;
}
__device__ __forceinline__ void st_cluster_v2(uint32_t addr, ull a, ull b) {
    asm volatile("st.shared::cluster.v2.u64 [%0], {%1, %2};" :: "r"(addr), "l"(a), "l"(b) : "memory");
}
__device__ __forceinline__ void mbar_init(uint32_t addr, uint32_t cnt) {
    asm volatile("mbarrier.init.shared.b64 [%0], %1;" :: "r"(addr), "r"(cnt) : "memory");
}
__device__ __forceinline__ void mbar_arrive_local(uint32_t addr) {
    asm volatile("mbarrier.arrive.release.cta.shared::cta.b64 _, [%0];" :: "r"(addr) : "memory");
}
__device__ __forceinline__ void mbar_arrive_remote(uint32_t addr) {
    asm volatile("mbarrier.arrive.release.cluster.shared::cluster.b64 _, [%0];" :: "r"(addr) : "memory");
}
__device__ __forceinline__ void mbar_wait_cta(uint32_t addr, uint32_t ph) {
    uint32_t done;
    do {
        asm volatile("{\n\t.reg .pred p;\n\t"
                     "mbarrier.try_wait.parity.acquire.cta.shared::cta.b64 p, [%1], %2, 0x989680;\n\t"
                     "selp.b32 %0, 1, 0, p;\n\t}"
                     : "=r"(done) : "r"(addr), "r"(ph) : "memory");
    } while (!done);
}
__device__ __forceinline__ void mbar_wait_cluster(uint32_t addr, uint32_t ph) {
    uint32_t done;
    do {
        asm volatile("{\n\t.reg .pred p;\n\t"
                     "mbarrier.try_wait.parity.acquire.cluster.shared::cta.b64 p, [%1], %2, 0x989680;\n\t"
                     "selp.b32 %0, 1, 0, p;\n\t}"
                     : "=r"(done) : "r"(addr), "r"(ph) : "memory");
    } while (!done);
}
__device__ __forceinline__ void cluster_sync() {
    asm volatile("barrier.cluster.arrive.aligned;" ::: "memory");
    asm volatile("barrier.cluster.wait.aligned;"   ::: "memory");
}

__device__ float    g_psum[NPROBES] = {0.f, 0.f, 0.f, 0.f};
__device__ unsigned g_ticket        = 0u;

// dynamic smem (bytes):
//   [0, 32768)      halo  : ull[2][32][64]  one row per warp, buf = t&1
//   [32768, 33792)  rbufA : ull[2][64]      row from rank-1 (my "above")
//   [33792, 34816)  rbufB : ull[2][64]      row from rank+1 (my "below")
//   [34816, 35840)  xsh   : float[256]
//   [35840, 36352)  wmbar : ull[32][2]
#define OFF_RBUFA 32768
#define OFF_RBUFB 33792
#define OFF_XSH   34816
#define OFF_WMBAR 35840
#define SMEM_BYTES 36368

__global__ __launch_bounds__(NTHREADS, 1) __cluster_dims__(CLUSTER, 1, 1)
void wave_fused_kernel(const float* __restrict__ x,
                       const float* __restrict__ c,
                       const int* __restrict__ probes_i32,
                       float* __restrict__ out)
{
    extern __shared__ char smem_raw[];
    ull*   halo  = reinterpret_cast<ull*>(smem_raw);
    ull*   rbufA = reinterpret_cast<ull*>(smem_raw + OFF_RBUFA);
    ull*   rbufB = reinterpret_cast<ull*>(smem_raw + OFF_RBUFB);
    float* xsh   = reinterpret_cast<float*>(smem_raw + OFF_XSH);

    const uint32_t smem_base  = smem_u32(smem_raw);
    const uint32_t wmbar_base = smem_base + OFF_WMBAR;   // wmbar[w][bi] at +(w*2+bi)*8

    uint32_t rank; asm("mov.u32 %0, %%cluster_ctarank;" : "=r"(rank));
    const int b   = blockIdx.x >> 2;          // batch = cluster id
    const int tid = threadIdx.x;
    const int w   = tid >> 5;                 // warp 0..31 : local row w
    const int l   = tid & 31;                 // lane       : cols 4l..4l+3
    const int c0  = l << 2;
    const int gr  = (int)rank * 32 + w;       // my global row

    // constants (reference-exact, folded by invd)
    const float dtb   = 0.5f * 0.005f;
    const float cy2s  = -1.0f - dtb;                   // -1.0025
    const float denom = 4.0f + (0.5f * 0.005f) / 0.5f; // 4.005
    const float invd  = 1.0f / denom;

    const ull NEG4  = pack2(-4.0f, -4.0f);
    const ull CY2P  = pack2(cy2s * invd, cy2s * invd);
    const ull TWO2P = pack2(2.0f * invd, 2.0f * invd);

    for (int t = tid; t < T_STEPS; t += NTHREADS)
        xsh[t] = x[t * BATCH + b];
    for (int i = tid; i < 2 * 32 * 64; i += NTHREADS)
        halo[i] = 0ull;
    for (int i = tid; i < 2 * 64; i += NTHREADS) { rbufA[i] = 0ull; rbufB[i] = 0ull; }

    // kk' = 0.25*c^2*invd for my single row
    ull kkx, kky, y1lo, y1hi, y2lo, y2hi;
    {
        float4 cv = *reinterpret_cast<const float4*>(&c[gr * 128 + c0]);
        kkx = pack2(0.25f * cv.x * cv.x * invd, 0.25f * cv.y * cv.y * invd);
        kky = pack2(0.25f * cv.z * cv.z * invd, 0.25f * cv.w * cv.w * invd);
        y1lo = 0ull; y1hi = 0ull; y2lo = 0ull; y2hi = 0ull;
    }

    // ---- probe decoding (runtime dtype detection: int32 vs int64) ----
    int pxv[NPROBES], pyv[NPROBES];
    {
        int odd_or = probes_i32[1] | probes_i32[3] | probes_i32[5] | probes_i32[7];
        if (odd_or == 0) {
#pragma unroll
            for (int p = 0; p < NPROBES; p++) { pxv[p] = probes_i32[4 * p]; pyv[p] = probes_i32[4 * p + 2]; }
        } else {
#pragma unroll
            for (int p = 0; p < NPROBES; p++) { pxv[p] = probes_i32[2 * p]; pyv[p] = probes_i32[2 * p + 1]; }
        }
    }
    float pacc[NPROBES];
    int   pidx[NPROBES];          // comp 0..3, or -1
    bool  pown = false;
#pragma unroll
    for (int p = 0; p < NPROBES; p++) {
        pacc[p] = 0.f;
        bool mine = (pxv[p] == gr) && (pyv[p] >= c0) && (pyv[p] < c0 + 4);
        pidx[p] = mine ? (pyv[p] - c0) : -1;
        pown = pown || mine;
    }

    // source (64,64): global row 64 = rank 2, w 0; col 64 -> lane 16, comp 0
    const bool src_owner = (rank == 2) && (w == 0) && (l == 16);

    // cluster seam roles
    const bool top_edge = (w == 0)  && (rank > 0);            // reads rbufA, pushes up
    const bool bot_edge = (w == 31) && (rank < CLUSTER - 1);  // reads rbufB, pushes down
    const uint32_t up_rank = (rank > 0) ? rank - 1 : 0;
    const uint32_t dn_rank = (rank < CLUSTER - 1) ? rank + 1 : rank;
    // rank r w0  pushes its row to rank r-1's rbufB and arrives rank r-1 wmbar[31]
    // rank r w31 pushes its row to rank r+1's rbufA and arrives rank r+1 wmbar[0]
    const uint32_t peer_up_rbuf  = mapa_u32(smem_base + OFF_RBUFB, up_rank);
    const uint32_t peer_up_mbar  = mapa_u32(wmbar_base + (31 * 2) * 8, up_rank);
    const uint32_t peer_dn_rbuf  = mapa_u32(smem_base + OFF_RBUFA, dn_rank);
    const uint32_t peer_dn_mbar  = mapa_u32(wmbar_base + (0 * 2) * 8, dn_rank);

    const uint32_t my_mbar = wmbar_base + (w * 2) * 8;
    const uint32_t up_mbar = wmbar_base + ((w - 1) * 2) * 8;
    const uint32_t dn_mbar = wmbar_base + ((w + 1) * 2) * 8;

    // init my two mbars: arrivals = 32 per producer warp feeding me
    if (l == 0) {
        uint32_t cnt = 0;
        cnt += (w > 0 || rank > 0) ? 32 : 0;              // above producer
        cnt += (w < 31 || rank < CLUSTER - 1) ? 32 : 0;   // below producer
        mbar_init(my_mbar, cnt);
        mbar_init(my_mbar + 8, cnt);
    }
    const bool has_remote = top_edge || bot_edge;

    __syncthreads();   // local init + smem zero done
    cluster_sync();    // visible cluster-wide before any remote arrive

    for (int t = 0; t < T_STEPS; t++) {
        const int rdbuf = (t + 1) & 1;   // buffer with step t-1 data
        const int wrbuf = t & 1;

        // single HW-sleep wait for both neighbors' step-(t-1) data
        if (t > 0) {
            const uint32_t mb = my_mbar + ((t - 1) & 1) * 8;
            const uint32_t ph = ((t - 1) >> 1) & 1;
            if (has_remote) mbar_wait_cluster(mb, ph);
            else            mbar_wait_cta(mb, ph);
        }

        // neighbor rows
        ull ab_lo = 0, ab_hi = 0, bl_lo = 0, bl_hi = 0;
        if (w > 0) {
            ulonglong2 h = *reinterpret_cast<const ulonglong2*>(
                &halo[rdbuf * 2048 + (w - 1) * 64 + 2 * l]);
            ab_lo = h.x; ab_hi = h.y;
        } else if (top_edge) {
            ulonglong2 h = *reinterpret_cast<const ulonglong2*>(&rbufA[rdbuf * 64 + 2 * l]);
            ab_lo = h.x; ab_hi = h.y;
        }
        if (w < 31) {
            ulonglong2 h = *reinterpret_cast<const ulonglong2*>(
                &halo[rdbuf * 2048 + (w + 1) * 64 + 2 * l]);
            bl_lo = h.x; bl_hi = h.y;
        } else if (bot_edge) {
            ulonglong2 h = *reinterpret_cast<const ulonglong2*>(&rbufB[rdbuf * 64 + 2 * l]);
            bl_lo = h.x; bl_hi = h.y;
        }

        // update my row
        {
            const ull v_lo = y1lo, v_hi = y1hi;
            float vx, vy, vz, vw;
            unpack2(v_lo, vx, vy);
            unpack2(v_hi, vz, vw);

            float lf = __shfl_up_sync(FULLM, vw, 1);
            float rt = __shfl_down_sync(FULLM, vx, 1);
            if (l == 0)  lf = 0.f;
            if (l == 31) rt = 0.f;

            const ull P1 = pack2(lf, vx);
            const ull P2 = pack2(vy, vz);
            const ull P3 = pack2(vw, rt);

            ull lap_lo = add2(add2(ab_lo, bl_lo), add2(P1, P2));
            lap_lo = fma2(NEG4, v_lo, lap_lo);
            ull lap_hi = add2(add2(ab_hi, bl_hi), add2(P2, P3));
            lap_hi = fma2(NEG4, v_hi, lap_hi);

            ull nv_lo = fma2(kkx, lap_lo, fma2(CY2P, y2lo, TWO2P));
            ull nv_hi = fma2(kky, lap_hi, fma2(CY2P, y2hi, TWO2P));

            if (src_owner) {
                float a, b2; unpack2(nv_lo, a, b2);
                nv_lo = pack2(a + xsh[t], b2);
            }

            y2lo = v_lo;  y2hi = v_hi;
            y1lo = nv_lo; y1hi = nv_hi;
        }

        // probe accumulation (<=4 owning threads)
        if (pown) {
#pragma unroll
            for (int p = 0; p < NPROBES; p++) {
                if (pidx[p] >= 0) {
                    float a, bf, val = 0.f;
                    switch (pidx[p]) {
                        case 0: unpack2(y1lo, a, bf); val = a;  break;
                        case 1: unpack2(y1lo, a, bf); val = bf; break;
                        case 2: unpack2(y1hi, a, bf); val = a;  break;
                        case 3: unpack2(y1hi, a, bf); val = bf; break;
                    }
                    pacc[p] += val * val;
                }
            }
        }

        // publish my row + arrive on consumers (skip after last step)
        if (t < T_STEPS - 1) {
            ulonglong2 rv; rv.x = y1lo; rv.y = y1hi;
            *reinterpret_cast<ulonglong2*>(&halo[wrbuf * 2048 + w * 64 + 2 * l]) = rv;

            if (w > 0)  mbar_arrive_local(up_mbar + wrbuf * 8);
            if (w < 31) mbar_arrive_local(dn_mbar + wrbuf * 8);

            if (top_edge) {
                st_cluster_v2(peer_up_rbuf + (wrbuf * 64 + 2 * l) * 8, y1lo, y1hi);
                mbar_arrive_remote(peer_up_mbar + wrbuf * 8);
            }
            if (bot_edge) {
                st_cluster_v2(peer_dn_rbuf + (wrbuf * 64 + 2 * l) * 8, y1lo, y1hi);
                mbar_arrive_remote(peer_dn_mbar + wrbuf * 8);
            }
        }
    }

#pragma unroll
    for (int p = 0; p < NPROBES; p++)
        if (pidx[p] >= 0) atomicAdd(&g_psum[p], pacc[p]);

    // fused finalization: last of 32 CTAs reduces, writes out, resets globals
    __syncthreads();
    __threadfence();
    if (tid == 0) {
        unsigned ticket = atomicAdd(&g_ticket, 1u);
        if (ticket == NCTAS - 1) {
            float v[NPROBES];
            float s = 0.f;
#pragma unroll
            for (int p = 0; p < NPROBES; p++) { v[p] = atomicAdd(&g_psum[p], 0.0f); s += v[p]; }
#pragma unroll
            for (int p = 0; p < NPROBES; p++) {
                out[p] = v[p] / s;
                atomicExch(&g_psum[p], 0.0f);
            }
            atomicExch(&g_ticket, 0u);
        }
    }
}

extern "C" void kernel_launch(void* const* d_in, const int* in_sizes, int n_in,
                              void* d_out, int out_size)
{
    const float* x      = (const float*)d_in[0];   // (256, 8) f32
    const float* c      = (const float*)d_in[1];   // (128, 128) f32
    const int*   probes = (const int*)d_in[2];     // (4, 2) i32/i64 — detected in-kernel
    float*       out    = (float*)d_out;           // (4,) f32

    cudaFuncSetAttribute(wave_fused_kernel,
                         cudaFuncAttributeMaxDynamicSharedMemorySize, SMEM_BYTES);

    wave_fused_kernel<<<NCTAS, NTHREADS, SMEM_BYTES>>>(x, c, probes, out);
}